// round 9
// baseline (speedup 1.0000x reference)
#include <cuda_runtime.h>
#include <cuda_fp16.h>
#include <cuda_bf16.h>
#include <mma.h>
#include <cstdint>

using namespace nvcuda;

#define N_NODES 100000
#define N_EDGES 3200000
#define IN_F    256
#define OUT_F   128
#define NEG_SLOPE 0.2f

#define SCAN_BLK 1024
#define NB ((N_NODES + SCAN_BLK - 1) / SCAN_BLK)

// Scratch (static __device__ globals per allocation rules)
__device__ __half g_support_h[(size_t)N_NODES * OUT_F];     // 25.6 MB fp16 support
__device__ ulonglong2 g_sorted2[(N_EDGES + 1) / 2];         // 16B-aligned packed records
__device__ int g_count[N_NODES];
__device__ int g_start[N_NODES + 1];
__device__ int g_cursor[N_NODES];
__device__ int g_bsum[NB];
__device__ int g_boff[NB];

// ---------------------------------------------------------------------------
// Kernel 1: fp16 tensor-core GEMM + LeakyReLU, fp16 epilogue.
// Double-buffered smem stages: MMA on stage i&1 overlaps global prefetch of
// tile i+1 and its smem store into stage (i+1)&1. One sync per K-step.
// ---------------------------------------------------------------------------
#define GBM 128
#define GKC 32
#define K_ITERS (IN_F / GKC)     // 8
#define A_LD 40                  // KC + 8 pad (fp16 elems)
#define C_LD 68                  // 64 + 4 pad (fp32 elems)

__global__ __launch_bounds__(256) void gemm_tc_kernel(
    const float* __restrict__ F, const float* __restrict__ W)
{
    __shared__ union {
        struct {
            __half Ah[2][GBM * A_LD];    // 2 x 10 KB
            __half Bh[2][OUT_F * A_LD];  // 2 x 10 KB
        } op;                            // 40 KB
        float Cs[GBM * C_LD];            // 34.8 KB (epilogue staging, half N)
    } sm;

    const int tid = threadIdx.x;
    const int wid = tid >> 5;
    const int wm  = wid & 3;        // warp row (4): rows wm*32..+32
    const int wn  = wid >> 2;       // warp col (2): cols wn*64..+64
    const int block_row = blockIdx.x * GBM;

    const int a_r  = tid >> 3;      // 0..31 (+t*32)
    const int a_c4 = tid & 7;

    wmma::fragment<wmma::accumulator, 16, 16, 16, float> acc[2][4];
#pragma unroll
    for (int i = 0; i < 2; ++i)
#pragma unroll
        for (int j = 0; j < 4; ++j) wmma::fill_fragment(acc[i][j], 0.f);

    float4 aReg[4], bReg[4];

    auto loadA = [&](int t, int k0) -> float4 {
        int r = a_r + t * 32;
        int grow = block_row + r;
        if (grow < N_NODES)
            return *reinterpret_cast<const float4*>(F + (size_t)grow * IN_F + k0 + a_c4 * 4);
        return make_float4(0.f, 0.f, 0.f, 0.f);
    };
    auto loadB = [&](int t, int k0) -> float4 {
        int n = a_r + t * 32;
        return *reinterpret_cast<const float4*>(W + (size_t)n * IN_F + k0 + a_c4 * 4);
    };
    auto storeStage = [&](int s) {
#pragma unroll
        for (int t = 0; t < 4; ++t) {
            int r = a_r + t * 32;
            __half2* ap = reinterpret_cast<__half2*>(&sm.op.Ah[s][r * A_LD + a_c4 * 4]);
            __half2* bp = reinterpret_cast<__half2*>(&sm.op.Bh[s][r * A_LD + a_c4 * 4]);
            ap[0] = __floats2half2_rn(aReg[t].x, aReg[t].y);
            ap[1] = __floats2half2_rn(aReg[t].z, aReg[t].w);
            bp[0] = __floats2half2_rn(bReg[t].x, bReg[t].y);
            bp[1] = __floats2half2_rn(bReg[t].z, bReg[t].w);
        }
    };

    // prologue: tile 0 -> stage 0
#pragma unroll
    for (int t = 0; t < 4; ++t) { aReg[t] = loadA(t, 0); bReg[t] = loadB(t, 0); }
    storeStage(0);
    __syncthreads();

#pragma unroll 1
    for (int it = 0; it < K_ITERS; ++it) {
        const int cur = it & 1;

        // prefetch next tile into registers (overlaps with MMAs below)
        if (it + 1 < K_ITERS) {
            int k0 = (it + 1) * GKC;
#pragma unroll
            for (int t = 0; t < 4; ++t) { aReg[t] = loadA(t, k0); bReg[t] = loadB(t, k0); }
        }

        // MMAs on current stage
#pragma unroll
        for (int kk = 0; kk < GKC; kk += 16) {
            wmma::fragment<wmma::matrix_a, 16, 16, 16, __half, wmma::row_major> a_f[2];
#pragma unroll
            for (int i = 0; i < 2; ++i)
                wmma::load_matrix_sync(a_f[i], &sm.op.Ah[cur][(wm * 32 + i * 16) * A_LD + kk], A_LD);
#pragma unroll
            for (int j = 0; j < 4; ++j) {
                wmma::fragment<wmma::matrix_b, 16, 16, 16, __half, wmma::col_major> b_f;
                wmma::load_matrix_sync(b_f, &sm.op.Bh[cur][(wn * 64 + j * 16) * A_LD + kk], A_LD);
#pragma unroll
                for (int i = 0; i < 2; ++i)
                    wmma::mma_sync(acc[i][j], a_f[i], b_f, acc[i][j]);
            }
        }

        // store next tile into the other stage (no conflict with current MMA reads)
        if (it + 1 < K_ITERS) storeStage((it + 1) & 1);
        __syncthreads();
    }

    // Epilogue: two column-half passes through 128x64 fp32 staging.
#pragma unroll
    for (int p = 0; p < 2; ++p) {
        if (wn == p) {
#pragma unroll
            for (int i = 0; i < 2; ++i)
#pragma unroll
                for (int j = 0; j < 4; ++j)
                    wmma::store_matrix_sync(&sm.Cs[(wm * 32 + i * 16) * C_LD + j * 16],
                                            acc[i][j], C_LD, wmma::mem_row_major);
        }
        __syncthreads();
#pragma unroll
        for (int t = 0; t < 16; ++t) {
            int idx = tid + t * 256;        // 0..4095
            int r   = idx >> 5;             // 0..127
            int h2  = idx & 31;             // 0..31
            int grow = block_row + r;
            if (grow < N_NODES) {
                float x0 = sm.Cs[r * C_LD + h2 * 2 + 0];
                float x1 = sm.Cs[r * C_LD + h2 * 2 + 1];
                x0 = (x0 > 0.f) ? x0 : NEG_SLOPE * x0;
                x1 = (x1 > 0.f) ? x1 : NEG_SLOPE * x1;
                __half2* dst = reinterpret_cast<__half2*>(
                    g_support_h + (size_t)grow * OUT_F + p * 64);
                dst[h2] = __floats2half2_rn(x0, x1);
            }
        }
        __syncthreads();
    }
}

// ---------------------------------------------------------------------------
// Histogram of destination rows
// ---------------------------------------------------------------------------
__global__ __launch_bounds__(256) void hist_kernel(const int* __restrict__ rows)
{
    int e = blockIdx.x * blockDim.x + threadIdx.x;
    if (e < N_EDGES) atomicAdd(&g_count[rows[e]], 1);
}

// ---------------------------------------------------------------------------
// Parallel 3-phase scan
// ---------------------------------------------------------------------------
__global__ __launch_bounds__(SCAN_BLK) void scan_reduce_kernel()
{
    __shared__ int wsum[32];
    const int tid = threadIdx.x;
    const int i = blockIdx.x * SCAN_BLK + tid;
    int v = (i < N_NODES) ? g_count[i] : 0;
#pragma unroll
    for (int d = 16; d > 0; d >>= 1) v += __shfl_down_sync(0xffffffffu, v, d);
    if ((tid & 31) == 0) wsum[tid >> 5] = v;
    __syncthreads();
    if (tid < 32) {
        int s = wsum[tid];
#pragma unroll
        for (int d = 16; d > 0; d >>= 1) s += __shfl_down_sync(0xffffffffu, s, d);
        if (tid == 0) g_bsum[blockIdx.x] = s;
    }
}

__global__ __launch_bounds__(128) void scan_bsums_kernel()
{
    __shared__ int wsum[4];
    const int tid  = threadIdx.x;
    const int lane = tid & 31;
    const int wid  = tid >> 5;
    int v = (tid < NB) ? g_bsum[tid] : 0;
    int x = v;
#pragma unroll
    for (int d = 1; d < 32; d <<= 1) {
        int t = __shfl_up_sync(0xffffffffu, x, d);
        if (lane >= d) x += t;
    }
    if (lane == 31) wsum[wid] = x;
    __syncthreads();
    if (tid < 4) {
        int w = wsum[tid];
#pragma unroll
        for (int d = 1; d < 4; d <<= 1) {
            int t = __shfl_up_sync(0x0000000fu, w, d);
            if (tid >= d) w += t;
        }
        wsum[tid] = w;
    }
    __syncthreads();
    int excl = x - v + ((wid > 0) ? wsum[wid - 1] : 0);
    if (tid < NB) g_boff[tid] = excl;
    if (tid == 0) g_start[N_NODES] = N_EDGES;
}

__global__ __launch_bounds__(SCAN_BLK) void scan_final_kernel()
{
    __shared__ int wsum[32];
    const int tid  = threadIdx.x;
    const int lane = tid & 31;
    const int wid  = tid >> 5;
    const int i = blockIdx.x * SCAN_BLK + tid;
    int v = (i < N_NODES) ? g_count[i] : 0;
    int x = v;
#pragma unroll
    for (int d = 1; d < 32; d <<= 1) {
        int t = __shfl_up_sync(0xffffffffu, x, d);
        if (lane >= d) x += t;
    }
    if (lane == 31) wsum[wid] = x;
    __syncthreads();
    if (tid < 32) {
        int w = wsum[tid];
#pragma unroll
        for (int d = 1; d < 32; d <<= 1) {
            int t = __shfl_up_sync(0xffffffffu, w, d);
            if (tid >= d) w += t;
        }
        wsum[tid] = w;
    }
    __syncthreads();
    int excl = x - v + ((wid > 0) ? wsum[wid - 1] : 0) + g_boff[blockIdx.x];
    if (i < N_NODES) { g_start[i] = excl; g_cursor[i] = excl; }
}

// ---------------------------------------------------------------------------
// Bucket edges into row-sorted order (8B record writes into the 16B array)
// ---------------------------------------------------------------------------
__global__ __launch_bounds__(256) void bucket_kernel(
    const float* __restrict__ vals,
    const int*   __restrict__ rows,
    const int*   __restrict__ cols)
{
    int e = blockIdx.x * blockDim.x + threadIdx.x;
    if (e >= N_EDGES) return;
    int r = rows[e];
    int pos = atomicAdd(&g_cursor[r], 1);
    unsigned long long rec = (unsigned int)cols[e]
                           | ((unsigned long long)__float_as_uint(vals[e]) << 32);
    reinterpret_cast<unsigned long long*>(g_sorted2)[pos] = rec;
}

// ---------------------------------------------------------------------------
// Row accumulation: one warp per row; fp16 gathers (256B/edge), 8-deep MLP,
// 16B edge-record loads, fp32 register accumulators, single coalesced write.
// ---------------------------------------------------------------------------
__global__ __launch_bounds__(256) void row_accum_kernel(float* __restrict__ out)
{
    const int row  = blockIdx.x * 8 + (threadIdx.x >> 5);
    const int lane = threadIdx.x & 31;
    if (row >= N_NODES) return;

    const int beg = g_start[row];
    const int end = g_start[row + 1];

    const uint2* __restrict__ sup = reinterpret_cast<const uint2*>(g_support_h);
    const unsigned long long* __restrict__ srt =
        reinterpret_cast<const unsigned long long*>(g_sorted2);

    float a0 = 0.f, a1 = 0.f, a2 = 0.f, a3 = 0.f;

    auto accum1 = [&](unsigned long long e) {
        int   c = (int)(e & 0xffffffffu);
        float v = __uint_as_float((unsigned int)(e >> 32));
        uint2 p = sup[(size_t)c * 32 + lane];
        float2 f;
        f = __half22float2(*reinterpret_cast<__half2*>(&p.x)); a0 += v * f.x; a1 += v * f.y;
        f = __half22float2(*reinterpret_cast<__half2*>(&p.y)); a2 += v * f.x; a3 += v * f.y;
    };

    int i = beg;
    // peel to 16B alignment
    if ((i & 1) && i < end) { accum1(srt[i]); ++i; }

    const ulonglong2* __restrict__ srt2 = g_sorted2;

    // main: 8 edges per iteration (4 x 16B record loads, 8 independent gathers)
    for (; i + 7 < end; i += 8) {
        ulonglong2 q0 = srt2[(i >> 1) + 0];
        ulonglong2 q1 = srt2[(i >> 1) + 1];
        ulonglong2 q2 = srt2[(i >> 1) + 2];
        ulonglong2 q3 = srt2[(i >> 1) + 3];
        int c0 = (int)(q0.x & 0xffffffffu), c1 = (int)(q0.y & 0xffffffffu);
        int c2 = (int)(q1.x & 0xffffffffu), c3 = (int)(q1.y & 0xffffffffu);
        int c4 = (int)(q2.x & 0xffffffffu), c5 = (int)(q2.y & 0xffffffffu);
        int c6 = (int)(q3.x & 0xffffffffu), c7 = (int)(q3.y & 0xffffffffu);
        float v0 = __uint_as_float((unsigned int)(q0.x >> 32));
        float v1 = __uint_as_float((unsigned int)(q0.y >> 32));
        float v2 = __uint_as_float((unsigned int)(q1.x >> 32));
        float v3 = __uint_as_float((unsigned int)(q1.y >> 32));
        float v4 = __uint_as_float((unsigned int)(q2.x >> 32));
        float v5 = __uint_as_float((unsigned int)(q2.y >> 32));
        float v6 = __uint_as_float((unsigned int)(q3.x >> 32));
        float v7 = __uint_as_float((unsigned int)(q3.y >> 32));
        uint2 p0 = sup[(size_t)c0 * 32 + lane];
        uint2 p1 = sup[(size_t)c1 * 32 + lane];
        uint2 p2 = sup[(size_t)c2 * 32 + lane];
        uint2 p3 = sup[(size_t)c3 * 32 + lane];
        uint2 p4 = sup[(size_t)c4 * 32 + lane];
        uint2 p5 = sup[(size_t)c5 * 32 + lane];
        uint2 p6 = sup[(size_t)c6 * 32 + lane];
        uint2 p7 = sup[(size_t)c7 * 32 + lane];
        float2 f;
        f = __half22float2(*reinterpret_cast<__half2*>(&p0.x)); a0 += v0 * f.x; a1 += v0 * f.y;
        f = __half22float2(*reinterpret_cast<__half2*>(&p0.y)); a2 += v0 * f.x; a3 += v0 * f.y;
        f = __half22float2(*reinterpret_cast<__half2*>(&p1.x)); a0 += v1 * f.x; a1 += v1 * f.y;
        f = __half22float2(*reinterpret_cast<__half2*>(&p1.y)); a2 += v1 * f.x; a3 += v1 * f.y;
        f = __half22float2(*reinterpret_cast<__half2*>(&p2.x)); a0 += v2 * f.x; a1 += v2 * f.y;
        f = __half22float2(*reinterpret_cast<__half2*>(&p2.y)); a2 += v2 * f.x; a3 += v2 * f.y;
        f = __half22float2(*reinterpret_cast<__half2*>(&p3.x)); a0 += v3 * f.x; a1 += v3 * f.y;
        f = __half22float2(*reinterpret_cast<__half2*>(&p3.y)); a2 += v3 * f.x; a3 += v3 * f.y;
        f = __half22float2(*reinterpret_cast<__half2*>(&p4.x)); a0 += v4 * f.x; a1 += v4 * f.y;
        f = __half22float2(*reinterpret_cast<__half2*>(&p4.y)); a2 += v4 * f.x; a3 += v4 * f.y;
        f = __half22float2(*reinterpret_cast<__half2*>(&p5.x)); a0 += v5 * f.x; a1 += v5 * f.y;
        f = __half22float2(*reinterpret_cast<__half2*>(&p5.y)); a2 += v5 * f.x; a3 += v5 * f.y;
        f = __half22float2(*reinterpret_cast<__half2*>(&p6.x)); a0 += v6 * f.x; a1 += v6 * f.y;
        f = __half22float2(*reinterpret_cast<__half2*>(&p6.y)); a2 += v6 * f.x; a3 += v6 * f.y;
        f = __half22float2(*reinterpret_cast<__half2*>(&p7.x)); a0 += v7 * f.x; a1 += v7 * f.y;
        f = __half22float2(*reinterpret_cast<__half2*>(&p7.y)); a2 += v7 * f.x; a3 += v7 * f.y;
    }
    for (; i + 1 < end; i += 2) {
        ulonglong2 q = srt2[i >> 1];
        accum1(q.x);
        accum1(q.y);
    }
    if (i < end) accum1(srt[i]);

    reinterpret_cast<float4*>(out)[(size_t)row * 32 + lane] =
        make_float4(a0, a1, a2, a3);
}

// ---------------------------------------------------------------------------
// launch — GEMM concurrent with the edge-sort pipeline (fork/join via events)
// ---------------------------------------------------------------------------
extern "C" void kernel_launch(void* const* d_in, const int* in_sizes, int n_in,
                              void* d_out, int out_size)
{
    const float* features = (const float*)d_in[0];
    const float* weight   = (const float*)d_in[1];
    const float* evals    = (const float*)d_in[2];
    const int*   erows    = (const int*)d_in[3];
    const int*   ecols    = (const int*)d_in[4];
    float*       out      = (float*)d_out;

    static cudaStream_t s2 = nullptr;
    static cudaEvent_t evFork = nullptr, evJoin = nullptr;
    if (s2 == nullptr) {
        cudaStreamCreateWithFlags(&s2, cudaStreamNonBlocking);
        cudaEventCreateWithFlags(&evFork, cudaEventDisableTiming);
        cudaEventCreateWithFlags(&evJoin, cudaEventDisableTiming);
    }

    // fork
    cudaEventRecord(evFork, 0);
    cudaStreamWaitEvent(s2, evFork, 0);

    // Stream 0: tensor-core GEMM + lrelu -> g_support_h (fp16)
    gemm_tc_kernel<<<(N_NODES + GBM - 1) / GBM, 256, 0, 0>>>(features, weight);

    // Stream s2: counting sort of edges by destination row
    void* count_ptr = nullptr;
    cudaGetSymbolAddress(&count_ptr, g_count);
    cudaMemsetAsync(count_ptr, 0, sizeof(int) * N_NODES, s2);
    hist_kernel<<<(N_EDGES + 255) / 256, 256, 0, s2>>>(erows);
    scan_reduce_kernel<<<NB, SCAN_BLK, 0, s2>>>();
    scan_bsums_kernel<<<1, 128, 0, s2>>>();
    scan_final_kernel<<<NB, SCAN_BLK, 0, s2>>>();
    bucket_kernel<<<(N_EDGES + 255) / 256, 256, 0, s2>>>(evals, erows, ecols);

    // join
    cudaEventRecord(evJoin, s2);
    cudaStreamWaitEvent(0, evJoin, 0);

    // Owner-computes reduction: one warp per row, no atomics
    row_accum_kernel<<<(N_NODES + 7) / 8, 256, 0, 0>>>(out);
}